// round 16
// baseline (speedup 1.0000x reference)
#include <cuda_runtime.h>
#include <cuda_fp16.h>
#include <math.h>

#define HH    14
#define WW    14
#define NN    197
#define BB    8
#define DIMV  64
#define NHEAD 2
#define DH    32
#define NUU   1122
#define NPAIR (NN*NN)   // 38809
#define RELPAIRS 38416
#define RELU_ 729
#define WLMAX 4096
#define NWORK_UB 3250   // analytic nwork = 3131; margin (runtime guard still applies)
#define NATTNBLK 400
#define SCALE 0.17677669529663687f
#define SMEM_MAIN 49152   // sU 16KB + sXT 32KB (4 blocks/SM — load-bearing)

typedef unsigned long long ull;

// ---------------- scratch -------------------------------------------------------
__device__ float    g_xn[BB*NN*DIMV];
__device__ float    g_qk[BB*NN*2*DIMV];
__device__ float    g_attn[BB*NHEAD*NN*NN];
__device__ __half   g_T[(size_t)NPAIR*BB*DIMV];   // 39.7 MB  T[n,m,b,e] fp16
__device__ uint2    g_work[WLMAX];                // (rank offset s, u<<16|cnt)
__device__ int      g_nwork;

__device__ __forceinline__ int hfun(int a) { return 14 - abs(a - 13); }
__device__ __forceinline__ int cfun(int t) {
    return (t <= 13) ? (t*(t+1))/2 : 196 - ((27-t)*(28-t))/2;
}
__device__ __forceinline__ unsigned h2u(__half2 h) { return *reinterpret_cast<unsigned*>(&h); }

// analytic pair decode: (u, rank r) -> (n, m); exactly inverts the old k_fill map
__device__ __forceinline__ void decode_pair(int u, int r, int& n, int& m) {
    if (u < RELU_) {
        int dx = u / 27, dy = u % 27;
        int hy = hfun(dy);
        int xmin = max(0, dx - 13), ymin = max(0, dy - 13);
        int x = xmin + r / hy, y = ymin + r % hy;
        n = 1 + x*WW + y;
        m = 1 + (x - dx + 13)*WW + (y - dy + 13);
    } else if (u < RELU_ + NN) {
        n = 0; m = u - RELU_;
    } else {
        n = u - RELU_ - NN + 1; m = 0;
    }
}

#define FMA2(acc, a, b) asm("fma.rn.f32x2 %0, %1, %2, %0;" : "+l"(acc) : "l"(a), "l"(b))
#define DUP2(dst, s)    asm("mov.b64 %0, {%1, %1};" : "=l"(dst) : "r"(__float_as_uint(s)))
#define UNPK(lo, hi, v) asm("mov.b64 {%0,%1}, %2;" : "=r"(lo), "=r"(hi) : "l"(v))

// ================= setup kernel: plan | LN+QK (no fill needed) =================
__global__ void __launch_bounds__(256) k_setup(const float* __restrict__ x,
                                               const float* __restrict__ gamma,
                                               const float* __restrict__ beta,
                                               const float* __restrict__ wqk) {
    __shared__ union {
        struct { int scan[2048]; int wsum[8]; } plan;
        struct { float sxn[BB][DIMV]; float part[2][128][BB]; } ln;
    } sm;
    int bid = blockIdx.x, t = threadIdx.x;

    if (bid == 0) {
        // ---- plan: shuffle-based scan over ceil(cnt/16) ----
        int lane = t & 31, w = t >> 5;
        int base = t * 8;
        int vals[8];
        int lsum = 0;
        #pragma unroll
        for (int j = 0; j < 8; j++) {
            int i = base + j;
            int c = 0;
            if (i < RELU_)    c = hfun(i/27) * hfun(i%27);
            else if (i < NUU) c = 1;
            vals[j] = (c + 15) >> 4;
            lsum += vals[j];
        }
        int incl = lsum;
        #pragma unroll
        for (int off = 1; off < 32; off <<= 1) {
            int nv = __shfl_up_sync(0xffffffffu, incl, off);
            if (lane >= off) incl += nv;
        }
        if (lane == 31) sm.plan.wsum[w] = incl;
        __syncthreads();
        if (t < 8) {
            int v = sm.plan.wsum[t];
            #pragma unroll
            for (int off = 1; off < 8; off <<= 1) {
                int nv = __shfl_up_sync(0x000000ffu, v, off);
                if (t >= off) v += nv;
            }
            sm.plan.wsum[t] = v;
        }
        __syncthreads();
        int wexcl = (w > 0) ? sm.plan.wsum[w-1] : 0;
        int run = wexcl + incl - lsum;
        #pragma unroll
        for (int j = 0; j < 8; j++) {
            run += vals[j];
            sm.plan.scan[base + j] = run;   // inclusive scan
        }
        __syncthreads();
        const int* src = sm.plan.scan;
        for (int u = t; u < NUU; u += 256) {
            int cnt;
            if (u < RELU_) cnt = hfun(u/27) * hfun(u%27);
            else           cnt = 1;
            int eo = (u == 0) ? 0 : src[u-1];
            int j = 0;
            for (int s = 0; s < cnt; s += 16, j++) {
                int c = cnt - s; if (c > 16) c = 16;
                if (eo + j < WLMAX)
                    g_work[eo + j] = make_uint2((unsigned)s,
                                                ((unsigned)u << 16) | (unsigned)c);
            }
        }
        if (t == 0) g_nwork = min(src[NUU-1], WLMAX);
        return;
    }

    // ---- LN + QK : one block per token n, all 8 batches (split-d + combine) ----
    int n = bid - 1;
    int w = t >> 5, lane = t & 31;
    {
        const float* xr = x + ((size_t)(w*NN + n))*DIMV;
        float2 v = *(const float2*)(xr + 2*lane);
        float sum = v.x + v.y, sq = v.x*v.x + v.y*v.y;
        #pragma unroll
        for (int o = 16; o > 0; o >>= 1) {
            sum += __shfl_xor_sync(0xffffffffu, sum, o);
            sq  += __shfl_xor_sync(0xffffffffu, sq,  o);
        }
        float mu  = sum * (1.0f/DIMV);
        float var = sq  * (1.0f/DIMV) - mu*mu;
        float r   = rsqrtf(var + 1e-5f);
        float2 o2;
        o2.x = (v.x - mu) * r * gamma[2*lane]   + beta[2*lane];
        o2.y = (v.y - mu) * r * gamma[2*lane+1] + beta[2*lane+1];
        sm.ln.sxn[w][2*lane]   = o2.x;
        sm.ln.sxn[w][2*lane+1] = o2.y;
        *(float2*)(g_xn + ((size_t)(w*NN + n))*DIMV + 2*lane) = o2;
    }
    __syncthreads();
    int c = t & 127, half_ = t >> 7;
    float acc[BB];
    #pragma unroll
    for (int b = 0; b < BB; b++) acc[b] = 0.f;
    int d0 = half_ * 32;
    #pragma unroll 16
    for (int d = 0; d < 32; d++) {
        float wv = wqk[(d0 + d)*128 + c];
        #pragma unroll
        for (int b = 0; b < BB; b++) acc[b] += sm.ln.sxn[b][d0 + d] * wv;
    }
    #pragma unroll
    for (int b = 0; b < BB; b++) sm.ln.part[half_][c][b] = acc[b];
    __syncthreads();
    if (half_ == 0) {
        #pragma unroll
        for (int b = 0; b < BB; b++) {
            float v = sm.ln.part[0][c][b] + sm.ln.part[1][c][b];
            g_qk[((size_t)(b*NN + n))*128 + c] = v;
        }
    }
}

// ================= main kernel: attn [0,400) | pair GEMM [400,...) =============
__global__ void __launch_bounds__(256) k_mainattn(const float* __restrict__ up) {
    extern __shared__ __align__(16) char smx[];
    int bid = blockIdx.x;
    int tid = threadIdx.x, lane = tid & 31, w = tid >> 5;

    if (bid < NATTNBLK) {
        // ---------------- attention scores + softmax ----------------
        float* ks_s = (float*)smx;
        float* qs_s = ks_s + NN*33;
        float* red  = qs_s + DH;
        float* bc   = red + 8;
        int b  = bid / (NHEAD*25);
        int r  = bid % (NHEAD*25);
        int h  = r / 25;
        int nt = r % 25;
        for (int i = tid; i < NN*DH; i += 256) {
            int m = i >> 5, d = i & 31;
            ks_s[m*33 + d] = g_qk[(b*NN + m)*128 + 64 + h*DH + d];
        }
        __syncthreads();
        for (int k0 = 0; k0 < 8; k0++) {
            int n = nt*8 + k0;
            if (n >= NN) break;
            if (tid < DH) qs_s[tid] = g_qk[(b*NN + n)*128 + h*DH + tid];
            __syncthreads();
            float s = -3.0e38f;
            if (tid < NN) {
                float a = 0.f;
                #pragma unroll 8
                for (int d = 0; d < DH; d++) a += qs_s[d] * ks_s[tid*33 + d];
                s = a * SCALE;
            }
            float loc = s;
            #pragma unroll
            for (int o = 16; o > 0; o >>= 1) loc = fmaxf(loc, __shfl_xor_sync(0xffffffffu, loc, o));
            if (lane == 0) red[w] = loc;
            __syncthreads();
            if (tid == 0) {
                float m0 = red[0];
                #pragma unroll
                for (int i = 1; i < 8; i++) m0 = fmaxf(m0, red[i]);
                bc[0] = m0;
            }
            __syncthreads();
            float mx = bc[0];
            float p = (tid < NN) ? __expf(s - mx) : 0.f;
            float ls = p;
            #pragma unroll
            for (int o = 16; o > 0; o >>= 1) ls += __shfl_xor_sync(0xffffffffu, ls, o);
            if (lane == 0) red[w] = ls;
            __syncthreads();
            if (tid == 0) {
                float s0 = 0.f;
                #pragma unroll
                for (int i = 0; i < 8; i++) s0 += red[i];
                bc[0] = s0;
            }
            __syncthreads();
            float inv = 1.0f / bc[0];
            if (tid < NN) g_attn[(((size_t)b*NHEAD + h)*NN + n)*NN + tid] = p * inv;
            __syncthreads();
        }
        return;
    }

    // -------- pair GEMM: half-warp = 1 pair; analytic pair decode (no g_pairs) --
    int wid_ = bid - NATTNBLK;
    if (wid_ >= g_nwork) return;
    uint2 wk = g_work[wid_];
    int s0  = (int)wk.x;
    int u   = (int)(wk.y >> 16);
    int cnt = (int)(wk.y & 0xffffu);

    float* sU  = (float*)smx;                 // [64 d][64 e]
    float* sXT = sU + 4096;                   // [16 slots][64 d][8 b]

    const float* Up = up + (size_t)u * 4096;
    #pragma unroll
    for (int i = 0; i < 4; i++)
        *(float4*)&sU[tid*4 + i*1024] = *(const float4*)&Up[tid*4 + i*1024];

    // decode this warp's two pairs once
    int n0 = 0, m0 = 0, n1 = 0, m1 = 0;
    bool have0 = (2*w < cnt), have1 = (2*w + 1 < cnt);
    if (have0) decode_pair(u, s0 + 2*w,     n0, m0);
    if (have1) decode_pair(u, s0 + 2*w + 1, n1, m1);

    // stage x transposed, conflict-free: lane = (b = l>>2, dl = l&3), d = dl+4i
    {
        int b = lane >> 2, dl = lane & 3;
        #pragma unroll
        for (int pr = 0; pr < 2; pr++) {
            bool have = pr ? have1 : have0;
            int mm = pr ? m1 : m0;
            if (have) {
                const float* xr = g_xn + (b*NN + mm)*DIMV;
                float* dst = sXT + ((w*2 + pr)*64)*8 + b;
                #pragma unroll
                for (int i = 0; i < 16; i++) {
                    int d = dl + 4*i;
                    dst[d*8] = xr[d];
                }
            }
        }
    }

    // Early exit for empty warps BEFORE the barrier (arrive-or-exit semantics).
    if (!have0) return;
    __syncthreads();

    int hw = lane >> 4, l16 = lane & 15;
    int e4 = l16 * 4;
    const float* xbase = sXT + ((w*2 + hw)*64)*8;
    const float* ubase = sU + e4;

    ull acc[8][2];
    #pragma unroll
    for (int b = 0; b < 8; b++) { acc[b][0] = 0ull; acc[b][1] = 0ull; }

    #pragma unroll 4
    for (int d = 0; d < 64; d++) {
        ulonglong2 uu = *(const ulonglong2*)(ubase + d*64);
        float4 xa = *(const float4*)(xbase + d*8);
        float4 xb = *(const float4*)(xbase + d*8 + 4);
        ull x0,x1,x2,x3,x4,x5,x6,x7;
        DUP2(x0, xa.x); DUP2(x1, xa.y); DUP2(x2, xa.z); DUP2(x3, xa.w);
        DUP2(x4, xb.x); DUP2(x5, xb.y); DUP2(x6, xb.z); DUP2(x7, xb.w);
        FMA2(acc[0][0], x0, uu.x); FMA2(acc[0][1], x0, uu.y);
        FMA2(acc[1][0], x1, uu.x); FMA2(acc[1][1], x1, uu.y);
        FMA2(acc[2][0], x2, uu.x); FMA2(acc[2][1], x2, uu.y);
        FMA2(acc[3][0], x3, uu.x); FMA2(acc[3][1], x3, uu.y);
        FMA2(acc[4][0], x4, uu.x); FMA2(acc[4][1], x4, uu.y);
        FMA2(acc[5][0], x5, uu.x); FMA2(acc[5][1], x5, uu.y);
        FMA2(acc[6][0], x6, uu.x); FMA2(acc[6][1], x6, uu.y);
        FMA2(acc[7][0], x7, uu.x); FMA2(acc[7][1], x7, uu.y);
    }

    bool haveS = hw ? have1 : have0;
    if (haveS) {
        int n = hw ? n1 : n0, m = hw ? m1 : m0;
        size_t base = (size_t)(n*NN + m)*512 + e4;
        #pragma unroll
        for (int b = 0; b < 8; b++) {
            unsigned a0, a1, b0, b1;
            UNPK(a0, a1, acc[b][0]);
            UNPK(b0, b1, acc[b][1]);
            uint2 st;
            st.x = h2u(__floats2half2_rn(__uint_as_float(a0), __uint_as_float(a1)));
            st.y = h2u(__floats2half2_rn(__uint_as_float(b0), __uint_as_float(b1)));
            *(uint2*)&g_T[base + b*64] = st;
        }
    }
}

// ================= phase 2: attn-weighted sum + output projection ==============
__global__ void __launch_bounds__(256) k_out(const float* __restrict__ wout,
                                             const float* __restrict__ bout,
                                             float* __restrict__ out) {
    __shared__ float sA[2*200];
    __shared__ float2 sRed[8][32];
    __shared__ float sAcc[DIMV];
    int bid = blockIdx.x;
    int b = bid / NN, n = bid % NN;
    int t = threadIdx.x;
    int p = t & 31, q = t >> 5;
    for (int i = t; i < 2*NN; i += 256) {
        int h = i / NN, m = i % NN;
        sA[h*200 + m] = g_attn[(((size_t)b*NHEAD + h)*NN + n)*NN + m];
    }
    __syncthreads();
    int e = 2*p;
    int h = e >> 5;
    const __half2* Tb = (const __half2*)(g_T + (size_t)(n*NN)*(BB*DIMV) + b*DIMV + e);
    float2 acc; acc.x = 0.f; acc.y = 0.f;
    for (int m = q; m < NN; m += 8) {
        float a = sA[h*200 + m];
        float2 v = __half22float2(Tb[(size_t)m * (BB*DIMV/2)]);
        acc.x += a * v.x;
        acc.y += a * v.y;
    }
    sRed[q][p] = acc;
    __syncthreads();
    if (t < 32) {
        float2 s = sRed[0][t];
        #pragma unroll
        for (int j = 1; j < 8; j++) { s.x += sRed[j][t].x; s.y += sRed[j][t].y; }
        sAcc[2*t] = s.x; sAcc[2*t+1] = s.y;
    }
    __syncthreads();
    if (t < DIMV) {
        float r = bout[t];
        #pragma unroll 8
        for (int k = 0; k < DIMV; k++) r += sAcc[k] * wout[k*DIMV + t];
        out[((size_t)(b*NN + n))*DIMV + t] = r;
    }
}

// ---------------- launch -------------------------------------------------------
extern "C" void kernel_launch(void* const* d_in, const int* in_sizes, int n_in,
                              void* d_out, int out_size) {
    const float* x     = (const float*)d_in[0];
    const float* gamma = (const float*)d_in[1];
    const float* beta  = (const float*)d_in[2];
    const float* wqk   = (const float*)d_in[3];
    const float* up    = (const float*)d_in[4];
    const float* wout  = (const float*)d_in[5];
    const float* bout  = (const float*)d_in[6];
    float* out = (float*)d_out;

    cudaFuncSetAttribute(k_mainattn, cudaFuncAttributeMaxDynamicSharedMemorySize, SMEM_MAIN);

    k_setup   <<<1 + NN, 256>>>(x, gamma, beta, wqk);
    k_mainattn<<<NATTNBLK + NWORK_UB, 256, SMEM_MAIN>>>(up);
    k_out     <<<BB*NN, 256>>>(wout, bout, out);
}

// round 17
// speedup vs baseline: 1.8871x; 1.8871x over previous
#include <cuda_runtime.h>
#include <cuda_fp16.h>
#include <math.h>

#define HH    14
#define WW    14
#define NN    197
#define BB    8
#define DIMV  64
#define NHEAD 2
#define DH    32
#define NUU   1122
#define NPAIR (NN*NN)   // 38809
#define RELPAIRS 38416
#define RELU_ 729
#define WLMAX 4096
#define NWORK_UB 3250   // analytic nwork = 3131; margin 119 (runtime guard still applies)
#define NATTNBLK 400
#define SCALE 0.17677669529663687f
#define SMEM_MAIN 49152   // sU 16KB + sXT 32KB (4 blocks/SM — load-bearing)

typedef unsigned long long ull;

// ---------------- scratch -------------------------------------------------------
__device__ float    g_xn[BB*NN*DIMV];
__device__ float    g_qk[BB*NN*2*DIMV];
__device__ float    g_attn[BB*NHEAD*NN*NN];
__device__ __half   g_T[(size_t)NPAIR*BB*DIMV];   // 39.7 MB  T[n,m,b,e] fp16
__device__ unsigned g_pairs[NPAIR];
__device__ uint2    g_work[WLMAX];
__device__ int      g_nwork;

__device__ __forceinline__ int hfun(int a) { return 14 - abs(a - 13); }
__device__ __forceinline__ int cfun(int t) {
    return (t <= 13) ? (t*(t+1))/2 : 196 - ((27-t)*(28-t))/2;
}
__device__ __forceinline__ unsigned h2u(__half2 h) { return *reinterpret_cast<unsigned*>(&h); }

#define FMA2(acc, a, b) asm("fma.rn.f32x2 %0, %1, %2, %0;" : "+l"(acc) : "l"(a), "l"(b))
#define DUP2(dst, s)    asm("mov.b64 %0, {%1, %1};" : "=l"(dst) : "r"(__float_as_uint(s)))
#define UNPK(lo, hi, v) asm("mov.b64 {%0,%1}, %2;" : "=r"(lo), "=r"(hi) : "l"(v))

// ================= setup kernel: fill | plan | LN+QK ===========================
__global__ void __launch_bounds__(256) k_setup(const float* __restrict__ x,
                                               const float* __restrict__ gamma,
                                               const float* __restrict__ beta,
                                               const float* __restrict__ wqk) {
    __shared__ union {
        struct { int scan[2048]; int wsum[8]; } plan;
        struct { float sxn[BB][DIMV]; float part[2][128][BB]; } ln;
    } sm;
    int bid = blockIdx.x, t = threadIdx.x;

    if (bid < 152) {
        int i = bid*256 + t;
        if (i >= NPAIR) return;
        int n = i / NN, m = i % NN;
        int pos;
        if (n == 0)      pos = RELPAIRS + m;
        else if (m == 0) pos = RELPAIRS + NN + (n - 1);
        else {
            int xx = (n-1) / WW, yy = (n-1) % WW;
            int ii = (m-1) / WW, jj = (m-1) % WW;
            int dx = xx - ii + 13, dy = yy - jj + 13;
            int off = cfun(dx)*196 + hfun(dx)*cfun(dy);
            int xmin = max(0, dx-13), ymin = max(0, dy-13);
            pos = off + (xx - xmin)*hfun(dy) + (yy - ymin);
        }
        g_pairs[pos] = ((unsigned)n << 16) | (unsigned)m;
        return;
    }
    if (bid == 152) {
        // ---- plan: shuffle-based scan ----
        int lane = t & 31, w = t >> 5;
        int base = t * 8;
        int vals[8];
        int lsum = 0;
        #pragma unroll
        for (int j = 0; j < 8; j++) {
            int i = base + j;
            int c = 0;
            if (i < RELU_)    c = hfun(i/27) * hfun(i%27);
            else if (i < NUU) c = 1;
            vals[j] = (c + 15) >> 4;
            lsum += vals[j];
        }
        int incl = lsum;
        #pragma unroll
        for (int off = 1; off < 32; off <<= 1) {
            int nv = __shfl_up_sync(0xffffffffu, incl, off);
            if (lane >= off) incl += nv;
        }
        if (lane == 31) sm.plan.wsum[w] = incl;
        __syncthreads();
        if (t < 8) {
            int v = sm.plan.wsum[t];
            #pragma unroll
            for (int off = 1; off < 8; off <<= 1) {
                int nv = __shfl_up_sync(0x000000ffu, v, off);
                if (t >= off) v += nv;
            }
            sm.plan.wsum[t] = v;
        }
        __syncthreads();
        int wexcl = (w > 0) ? sm.plan.wsum[w-1] : 0;
        int run = wexcl + incl - lsum;
        #pragma unroll
        for (int j = 0; j < 8; j++) {
            run += vals[j];
            sm.plan.scan[base + j] = run;   // inclusive scan
        }
        __syncthreads();
        const int* src = sm.plan.scan;
        for (int u = t; u < NUU; u += 256) {
            int cnt, po;
            if (u < RELU_) {
                int dx = u/27, dy = u%27;
                cnt = hfun(dx)*hfun(dy);
                po  = cfun(dx)*196 + hfun(dx)*cfun(dy);
            } else if (u < RELU_ + NN) { cnt = 1; po = RELPAIRS + (u - RELU_); }
            else                       { cnt = 1; po = RELPAIRS + NN + (u - RELU_ - NN); }
            int eo = (u == 0) ? 0 : src[u-1];
            int j = 0;
            for (int s = 0; s < cnt; s += 16, j++) {
                int c = cnt - s; if (c > 16) c = 16;
                if (eo + j < WLMAX)
                    g_work[eo + j] = make_uint2((unsigned)(po + s),
                                                ((unsigned)u << 16) | (unsigned)c);
            }
        }
        if (t == 0) g_nwork = min(src[NUU-1], WLMAX);
        return;
    }

    // ---- LN + QK : one block per token n, all 8 batches (split-d + combine) ----
    int n = bid - 153;
    int w = t >> 5, lane = t & 31;
    {
        const float* xr = x + ((size_t)(w*NN + n))*DIMV;
        float2 v = *(const float2*)(xr + 2*lane);
        float sum = v.x + v.y, sq = v.x*v.x + v.y*v.y;
        #pragma unroll
        for (int o = 16; o > 0; o >>= 1) {
            sum += __shfl_xor_sync(0xffffffffu, sum, o);
            sq  += __shfl_xor_sync(0xffffffffu, sq,  o);
        }
        float mu  = sum * (1.0f/DIMV);
        float var = sq  * (1.0f/DIMV) - mu*mu;
        float r   = rsqrtf(var + 1e-5f);
        float2 o2;
        o2.x = (v.x - mu) * r * gamma[2*lane]   + beta[2*lane];
        o2.y = (v.y - mu) * r * gamma[2*lane+1] + beta[2*lane+1];
        sm.ln.sxn[w][2*lane]   = o2.x;
        sm.ln.sxn[w][2*lane+1] = o2.y;
        *(float2*)(g_xn + ((size_t)(w*NN + n))*DIMV + 2*lane) = o2;
    }
    __syncthreads();
    int c = t & 127, half_ = t >> 7;
    float acc[BB];
    #pragma unroll
    for (int b = 0; b < BB; b++) acc[b] = 0.f;
    int d0 = half_ * 32;
    #pragma unroll 16
    for (int d = 0; d < 32; d++) {
        float wv = wqk[(d0 + d)*128 + c];
        #pragma unroll
        for (int b = 0; b < BB; b++) acc[b] += sm.ln.sxn[b][d0 + d] * wv;
    }
    #pragma unroll
    for (int b = 0; b < BB; b++) sm.ln.part[half_][c][b] = acc[b];
    __syncthreads();
    if (half_ == 0) {
        #pragma unroll
        for (int b = 0; b < BB; b++) {
            float v = sm.ln.part[0][c][b] + sm.ln.part[1][c][b];
            g_qk[((size_t)(b*NN + n))*128 + c] = v;
        }
    }
}

// ================= main kernel: attn [0,400) | pair GEMM [400,...) =============
__global__ void __launch_bounds__(256) k_mainattn(const float* __restrict__ up) {
    extern __shared__ __align__(16) char smx[];
    int bid = blockIdx.x;
    int tid = threadIdx.x, lane = tid & 31, w = tid >> 5;

    if (bid < NATTNBLK) {
        // ---------------- attention scores + softmax ----------------
        float* ks_s = (float*)smx;
        float* qs_s = ks_s + NN*33;
        float* red  = qs_s + DH;
        float* bc   = red + 8;
        int b  = bid / (NHEAD*25);
        int r  = bid % (NHEAD*25);
        int h  = r / 25;
        int nt = r % 25;
        for (int i = tid; i < NN*DH; i += 256) {
            int m = i >> 5, d = i & 31;
            ks_s[m*33 + d] = g_qk[(b*NN + m)*128 + 64 + h*DH + d];
        }
        __syncthreads();
        for (int k0 = 0; k0 < 8; k0++) {
            int n = nt*8 + k0;
            if (n >= NN) break;
            if (tid < DH) qs_s[tid] = g_qk[(b*NN + n)*128 + h*DH + tid];
            __syncthreads();
            float s = -3.0e38f;
            if (tid < NN) {
                float a = 0.f;
                #pragma unroll 8
                for (int d = 0; d < DH; d++) a += qs_s[d] * ks_s[tid*33 + d];
                s = a * SCALE;
            }
            float loc = s;
            #pragma unroll
            for (int o = 16; o > 0; o >>= 1) loc = fmaxf(loc, __shfl_xor_sync(0xffffffffu, loc, o));
            if (lane == 0) red[w] = loc;
            __syncthreads();
            if (tid == 0) {
                float m0 = red[0];
                #pragma unroll
                for (int i = 1; i < 8; i++) m0 = fmaxf(m0, red[i]);
                bc[0] = m0;
            }
            __syncthreads();
            float mx = bc[0];
            float p = (tid < NN) ? __expf(s - mx) : 0.f;
            float ls = p;
            #pragma unroll
            for (int o = 16; o > 0; o >>= 1) ls += __shfl_xor_sync(0xffffffffu, ls, o);
            if (lane == 0) red[w] = ls;
            __syncthreads();
            if (tid == 0) {
                float s0 = 0.f;
                #pragma unroll
                for (int i = 0; i < 8; i++) s0 += red[i];
                bc[0] = s0;
            }
            __syncthreads();
            float inv = 1.0f / bc[0];
            if (tid < NN) g_attn[(((size_t)b*NHEAD + h)*NN + n)*NN + tid] = p * inv;
            __syncthreads();
        }
        return;
    }

    // -------- pair GEMM: half-warp = 1 pair, lane = 4 e-cols, acc pairs e ------
    int wid_ = bid - NATTNBLK;
    if (wid_ >= g_nwork) return;
    uint2 wk = g_work[wid_];
    int pairStart = (int)wk.x;
    int u   = (int)(wk.y >> 16);
    int cnt = (int)(wk.y & 0xffffu);

    float* sU  = (float*)smx;                 // [64 d][64 e]
    float* sXT = sU + 4096;                   // [16 slots][64 d][8 b]

    const float* Up = up + (size_t)u * 4096;
    #pragma unroll
    for (int i = 0; i < 4; i++)
        *(float4*)&sU[tid*4 + i*1024] = *(const float4*)&Up[tid*4 + i*1024];

    // stage x transposed, conflict-free: lane = (b = l>>2, dl = l&3), d = dl+4i
    {
        int b = lane >> 2, dl = lane & 3;
        #pragma unroll
        for (int pr = 0; pr < 2; pr++) {
            int pp = 2*w + pr;
            if (pp < cnt) {
                unsigned pk = g_pairs[pairStart + pp];
                int m = (int)(pk & 0xffffu);
                const float* xr = g_xn + (b*NN + m)*DIMV;
                float* dst = sXT + ((w*2 + pr)*64)*8 + b;
                #pragma unroll
                for (int i = 0; i < 16; i++) {
                    int d = dl + 4*i;
                    dst[d*8] = xr[d];
                }
            }
        }
    }

    // Early exit for empty warps BEFORE the barrier (arrive-or-exit semantics).
    if (2*w >= cnt) return;
    __syncthreads();

    int hw = lane >> 4, l16 = lane & 15;
    int e4 = l16 * 4;
    const float* xbase = sXT + ((w*2 + hw)*64)*8;
    const float* ubase = sU + e4;

    ull acc[8][2];
    #pragma unroll
    for (int b = 0; b < 8; b++) { acc[b][0] = 0ull; acc[b][1] = 0ull; }

    #pragma unroll 4
    for (int d = 0; d < 64; d++) {
        ulonglong2 uu = *(const ulonglong2*)(ubase + d*64);
        float4 xa = *(const float4*)(xbase + d*8);
        float4 xb = *(const float4*)(xbase + d*8 + 4);
        ull x0,x1,x2,x3,x4,x5,x6,x7;
        DUP2(x0, xa.x); DUP2(x1, xa.y); DUP2(x2, xa.z); DUP2(x3, xa.w);
        DUP2(x4, xb.x); DUP2(x5, xb.y); DUP2(x6, xb.z); DUP2(x7, xb.w);
        FMA2(acc[0][0], x0, uu.x); FMA2(acc[0][1], x0, uu.y);
        FMA2(acc[1][0], x1, uu.x); FMA2(acc[1][1], x1, uu.y);
        FMA2(acc[2][0], x2, uu.x); FMA2(acc[2][1], x2, uu.y);
        FMA2(acc[3][0], x3, uu.x); FMA2(acc[3][1], x3, uu.y);
        FMA2(acc[4][0], x4, uu.x); FMA2(acc[4][1], x4, uu.y);
        FMA2(acc[5][0], x5, uu.x); FMA2(acc[5][1], x5, uu.y);
        FMA2(acc[6][0], x6, uu.x); FMA2(acc[6][1], x6, uu.y);
        FMA2(acc[7][0], x7, uu.x); FMA2(acc[7][1], x7, uu.y);
    }

    int p = 2*w + hw;
    if (p < cnt) {
        unsigned pk = g_pairs[pairStart + p];
        int n = (int)(pk >> 16), m = (int)(pk & 0xffffu);
        size_t base = (size_t)(n*NN + m)*512 + e4;
        #pragma unroll
        for (int b = 0; b < 8; b++) {
            unsigned a0, a1, b0, b1;
            UNPK(a0, a1, acc[b][0]);
            UNPK(b0, b1, acc[b][1]);
            uint2 st;
            st.x = h2u(__floats2half2_rn(__uint_as_float(a0), __uint_as_float(a1)));
            st.y = h2u(__floats2half2_rn(__uint_as_float(b0), __uint_as_float(b1)));
            *(uint2*)&g_T[base + b*64] = st;
        }
    }
}

// ================= phase 2: attn-weighted sum + output projection ==============
__global__ void __launch_bounds__(256) k_out(const float* __restrict__ wout,
                                             const float* __restrict__ bout,
                                             float* __restrict__ out) {
    __shared__ float sA[2*200];
    __shared__ float2 sRed[8][32];
    __shared__ float sAcc[DIMV];
    int bid = blockIdx.x;
    int b = bid / NN, n = bid % NN;
    int t = threadIdx.x;
    int p = t & 31, q = t >> 5;
    for (int i = t; i < 2*NN; i += 256) {
        int h = i / NN, m = i % NN;
        sA[h*200 + m] = g_attn[(((size_t)b*NHEAD + h)*NN + n)*NN + m];
    }
    __syncthreads();
    int e = 2*p;
    int h = e >> 5;
    const __half2* Tb = (const __half2*)(g_T + (size_t)(n*NN)*(BB*DIMV) + b*DIMV + e);
    float2 acc; acc.x = 0.f; acc.y = 0.f;
    for (int m = q; m < NN; m += 8) {
        float a = sA[h*200 + m];
        float2 v = __half22float2(Tb[(size_t)m * (BB*DIMV/2)]);
        acc.x += a * v.x;
        acc.y += a * v.y;
    }
    sRed[q][p] = acc;
    __syncthreads();
    if (t < 32) {
        float2 s = sRed[0][t];
        #pragma unroll
        for (int j = 1; j < 8; j++) { s.x += sRed[j][t].x; s.y += sRed[j][t].y; }
        sAcc[2*t] = s.x; sAcc[2*t+1] = s.y;
    }
    __syncthreads();
    if (t < DIMV) {
        float r = bout[t];
        #pragma unroll 8
        for (int k = 0; k < DIMV; k++) r += sAcc[k] * wout[k*DIMV + t];
        out[((size_t)(b*NN + n))*DIMV + t] = r;
    }
}

// ---------------- launch -------------------------------------------------------
extern "C" void kernel_launch(void* const* d_in, const int* in_sizes, int n_in,
                              void* d_out, int out_size) {
    const float* x     = (const float*)d_in[0];
    const float* gamma = (const float*)d_in[1];
    const float* beta  = (const float*)d_in[2];
    const float* wqk   = (const float*)d_in[3];
    const float* up    = (const float*)d_in[4];
    const float* wout  = (const float*)d_in[5];
    const float* bout  = (const float*)d_in[6];
    float* out = (float*)d_out;

    cudaFuncSetAttribute(k_mainattn, cudaFuncAttributeMaxDynamicSharedMemorySize, SMEM_MAIN);

    k_setup   <<<153 + NN, 256>>>(x, gamma, beta, wqk);
    k_mainattn<<<NATTNBLK + NWORK_UB, 256, SMEM_MAIN>>>(up);
    k_out     <<<BB*NN, 256>>>(wout, bout, out);
}